// round 11
// baseline (speedup 1.0000x reference)
#include <cuda_runtime.h>

#define BB 256
#define TT 50
#define MM 20
#define EE 128
#define G3 384

typedef unsigned long long u64;

// scratch (no cudaMalloc allowed)
__device__ __align__(16) float g_ub[BB*TT*EE];   // basket means (B,T,E)

__device__ __forceinline__ void fma2(u64 &acc, u64 a, u64 b){
    asm("fma.rn.f32x2 %0, %1, %2, %0;" : "+l"(acc) : "l"(a), "l"(b));
}
__device__ __forceinline__ u64 add2(u64 a, u64 b){
    u64 r; asm("add.rn.f32x2 %0, %1, %2;" : "=l"(r) : "l"(a), "l"(b));
    return r;
}
__device__ __forceinline__ float hsum2(u64 v){
    float lo, hi;
    asm("mov.b64 {%0,%1}, %2;" : "=f"(lo), "=f"(hi) : "l"(v));
    return lo + hi;
}
__device__ __forceinline__ float sigf(float x){
    return __fdividef(1.f, 1.f + __expf(-x));
}
__device__ __forceinline__ float tanhfast(float x){
    return __fdividef(2.f, 1.f + __expf(-2.f*x)) - 1.f;
}
__device__ __forceinline__ int zero_dep(float x){
    int r;
    asm("{\n\t.reg .b32 t;\n\tmov.b32 t, %1;\n\tand.b32 %0, t, 0;\n\t}"
        : "=r"(r) : "f"(x));
    return r;
}

// dot of this thread's W row with a 128-float vector in SMEM (broadcast LDS)
__device__ __forceinline__ float dot_s(const u64* __restrict__ w,
                                       const float* __restrict__ src){
    u64 ca = 0ull, cb = 0ull;
    const ulonglong2* hp = (const ulonglong2*)src;
    #pragma unroll
    for (int k = 0; k < 32; ++k){
        ulonglong2 v = hp[k];
        fma2(ca, w[2*k  ], v.x);
        fma2(cb, w[2*k+1], v.y);
    }
    return hsum2(add2(ca, cb));
}
// same, src in global memory (uniform address -> L1 broadcast)
__device__ __forceinline__ float dot_g(const u64* __restrict__ w,
                                       const float* __restrict__ src){
    u64 ca = 0ull, cb = 0ull;
    const ulonglong2* hp = (const ulonglong2*)src;
    #pragma unroll
    for (int k = 0; k < 32; ++k){
        ulonglong2 v = __ldg(hp + k);
        fma2(ca, w[2*k  ], v.x);
        fma2(cb, w[2*k+1], v.y);
    }
    return hsum2(add2(ca, cb));
}

// ---------------------------------------------------------------------------
// K1: gather (measured ~5us, unchanged from R7)
// ---------------------------------------------------------------------------
#define RED20(FLD) \
    ((((v[0].FLD+v[1].FLD)+(v[2].FLD+v[3].FLD))+((v[4].FLD+v[5].FLD)+(v[6].FLD+v[7].FLD))) \
    +(((v[8].FLD+v[9].FLD)+(v[10].FLD+v[11].FLD))+((v[12].FLD+v[13].FLD)+(v[14].FLD+v[15].FLD))) \
    +((v[16].FLD+v[17].FLD)+(v[18].FLD+v[19].FLD)))

__global__ void __launch_bounds__(128,2) k_gather(const int* __restrict__ ids,
                                                  const int* __restrict__ bsz,
                                                  const int* __restrict__ lens,
                                                  const float* __restrict__ emb){
    const int p    = blockIdx.x * 4 + (threadIdx.x >> 5);   // 0..6399
    const int lane = threadIdx.x & 31;
    const float4* e4 = (const float4*)emb;

    const int r0 = p, r1 = 12799 - p;
    const int b0g = r0 / TT, t0g = r0 - b0g*TT;
    const int b1g = r1 / TT, t1g = r1 - b1g*TT;
    const bool act0 = t0g < __ldg(lens + b0g);
    const bool act1 = t1g < __ldg(lens + b1g);

    float4 v[20], u[20];
    if (act0){
        const int4* ip = (const int4*)(ids + r0*MM);
        const int4 i0=__ldg(ip), i1=__ldg(ip+1), i2=__ldg(ip+2),
                   i3=__ldg(ip+3), i4=__ldg(ip+4);
        v[0]=__ldg(e4+i0.x*32+lane);  v[1]=__ldg(e4+i0.y*32+lane);
        v[2]=__ldg(e4+i0.z*32+lane);  v[3]=__ldg(e4+i0.w*32+lane);
        v[4]=__ldg(e4+i1.x*32+lane);  v[5]=__ldg(e4+i1.y*32+lane);
        v[6]=__ldg(e4+i1.z*32+lane);  v[7]=__ldg(e4+i1.w*32+lane);
        v[8]=__ldg(e4+i2.x*32+lane);  v[9]=__ldg(e4+i2.y*32+lane);
        v[10]=__ldg(e4+i2.z*32+lane); v[11]=__ldg(e4+i2.w*32+lane);
        v[12]=__ldg(e4+i3.x*32+lane); v[13]=__ldg(e4+i3.y*32+lane);
        v[14]=__ldg(e4+i3.z*32+lane); v[15]=__ldg(e4+i3.w*32+lane);
        v[16]=__ldg(e4+i4.x*32+lane); v[17]=__ldg(e4+i4.y*32+lane);
        v[18]=__ldg(e4+i4.z*32+lane); v[19]=__ldg(e4+i4.w*32+lane);
    }
    if (act1){
        const int4* ip = (const int4*)(ids + r1*MM);
        const int4 i0=__ldg(ip), i1=__ldg(ip+1), i2=__ldg(ip+2),
                   i3=__ldg(ip+3), i4=__ldg(ip+4);
        u[0]=__ldg(e4+i0.x*32+lane);  u[1]=__ldg(e4+i0.y*32+lane);
        u[2]=__ldg(e4+i0.z*32+lane);  u[3]=__ldg(e4+i0.w*32+lane);
        u[4]=__ldg(e4+i1.x*32+lane);  u[5]=__ldg(e4+i1.y*32+lane);
        u[6]=__ldg(e4+i1.z*32+lane);  u[7]=__ldg(e4+i1.w*32+lane);
        u[8]=__ldg(e4+i2.x*32+lane);  u[9]=__ldg(e4+i2.y*32+lane);
        u[10]=__ldg(e4+i2.z*32+lane); u[11]=__ldg(e4+i2.w*32+lane);
        u[12]=__ldg(e4+i3.x*32+lane); u[13]=__ldg(e4+i3.y*32+lane);
        u[14]=__ldg(e4+i3.z*32+lane); u[15]=__ldg(e4+i3.w*32+lane);
        u[16]=__ldg(e4+i4.x*32+lane); u[17]=__ldg(e4+i4.y*32+lane);
        u[18]=__ldg(e4+i4.z*32+lane); u[19]=__ldg(e4+i4.w*32+lane);
    }
    if (act0){
        const float inv = 1.0f / (float)__ldg(bsz + r0);
        float4 a;
        a.x = RED20(x)*inv; a.y = RED20(y)*inv; a.z = RED20(z)*inv; a.w = RED20(w)*inv;
        ((float4*)g_ub)[r0*32 + lane] = a;
    }
    if (act1){
        #pragma unroll
        for (int k = 0; k < 20; ++k) v[k] = u[k];
        const float inv = 1.0f / (float)__ldg(bsz + r1);
        float4 a;
        a.x = RED20(x)*inv; a.y = RED20(y)*inv; a.z = RED20(z)*inv; a.w = RED20(w)*inv;
        ((float4*)g_ub)[r1*32 + lane] = a;
    }
}

// ---------------------------------------------------------------------------
// K2: fused xg + scan, R7 per-thread layout, STAGGERED half-step scan.
//  HS_A: dot row0@t (all threads)  || gates row1@t-1 (threads j<128)
//  HS_B: dot row1@t (if t<len1)    || gates row0@t   (threads j>=256)
// Row1's dot+gates execute only len1 times; gate tails overlap dot issue.
// SMEM: xg 2*50*384 + h 2*128 + hg 2*384 = 39424 floats = 157696 B
// ---------------------------------------------------------------------------
__global__ void __launch_bounds__(384,1) k_xgscan(
    const float* __restrict__ W_ih,
    const float* __restrict__ W_hh,
    const float* __restrict__ b_ih,
    const float* __restrict__ b_hh,
    const float* __restrict__ h0,
    const int*   __restrict__ lens,
    float*       __restrict__ out)
{
    extern __shared__ float smem[];
    float* s_xg  = smem;                   // [2][TT][G3]  (xg + b_ih)
    float* s_h   = s_xg + 2*TT*G3;         // [2][EE]
    float* s_hg0 = s_h + 2*EE;             // [G3]  (hg incl b_hh, row0)
    float* s_hg1 = s_hg0 + G3;             // [G3]  (row1)

    const int j  = threadIdx.x;
    const int b0 = blockIdx.x, b1 = (BB-1) - blockIdx.x;
    const int len0 = __ldg(lens + b0);     // lens sorted desc -> len0 >= len1
    const int len1 = __ldg(lens + b1);
    const int total = len0 + len1;

    u64 w[64];

    // ---------------- Phase B: xg -> SMEM (barrier-free) ----------------
    {
        const u64* wr = (const u64*)(W_ih + j*EE);
        #pragma unroll
        for (int k = 0; k < 64; ++k) w[k] = __ldg(wr + k);
    }
    {
        const float bi = __ldg(b_ih + j);
        for (int i = 0; i < total; ++i){
            const int rsel = (i >= len0);
            const int t    = rsel ? i - len0 : i;
            const float* src = g_ub + ((rsel ? b1 : b0)*TT + t)*EE;
            s_xg[(rsel*TT + t)*G3 + j] = dot_g(w, src) + bi;
        }
    }
    if (j < 256)
        s_h[j] = __ldg(h0 + ((j < EE) ? b0 : b1)*EE + (j & 127));
    __syncthreads();

    // ---------------- Phase C: staggered scan ----------------
    const int dep = zero_dep(s_xg[j]);     // keep W_hh loads after phase B
    {
        const u64* wr = (const u64*)(W_hh + (j + dep)*EE);
        #pragma unroll
        for (int k = 0; k < 64; ++k) w[k] = __ldg(wr + k);
    }
    const float bh = __ldg(b_hh + j);

    for (int t = 0; t < len0; ++t){
        // HS_A: dot row0@t ; gates row1@(t-1)
        const float f = dot_s(w, s_h) + bh;
        if (j < EE && t >= 1 && t <= len1){
            const int e = j;
            const float* xr = s_xg + (TT + (t-1))*G3;
            const float r  = sigf(xr[e]       + s_hg1[e]);
            const float z  = sigf(xr[e + 128] + s_hg1[e + 128]);
            const float n  = tanhfast(xr[e + 256] + r * s_hg1[e + 256]);
            const float hv = (1.f - z)*n + z * s_h[EE + e];
            s_h[EE + e] = hv;
            out[(b1*TT + (t-1))*EE + e] = hv;
        }
        s_hg0[j] = f;
        __syncthreads();

        // HS_B: dot row1@t ; gates row0@t
        if (t < len1)
            s_hg1[j] = dot_s(w, s_h + EE) + bh;
        if (j >= 256){
            const int e = j - 256;
            const float* xr = s_xg + t*G3;
            const float r  = sigf(xr[e]       + s_hg0[e]);
            const float z  = sigf(xr[e + 128] + s_hg0[e + 128]);
            const float n  = tanhfast(xr[e + 256] + r * s_hg0[e + 256]);
            const float hv = (1.f - z)*n + z * s_h[e];
            s_h[e] = hv;
            out[(b0*TT + t)*EE + e] = hv;
        }
        __syncthreads();
    }

    // pending final row1 gate when len1 == len0
    if (len1 == len0){
        if (j < EE){
            const int e = j, t = len0 - 1;
            const float* xr = s_xg + (TT + t)*G3;
            const float r  = sigf(xr[e]       + s_hg1[e]);
            const float z  = sigf(xr[e + 128] + s_hg1[e + 128]);
            const float n  = tanhfast(xr[e + 256] + r * s_hg1[e + 256]);
            const float hv = (1.f - z)*n + z * s_h[EE + e];
            s_h[EE + e] = hv;
            out[(b1*TT + t)*EE + e] = hv;
        }
        __syncthreads();
    }

    // ---------------- epilogue: masked tail zeros + h_u ----------------
    {
        const float4 z4 = make_float4(0.f, 0.f, 0.f, 0.f);
        float4* p0 = (float4*)(out + (b0*TT + len0)*EE);
        const int n0 = (TT - len0) * (EE/4);
        for (int k = j; k < n0; k += 384) p0[k] = z4;
        float4* p1 = (float4*)(out + (b1*TT + len1)*EE);
        const int n1 = (TT - len1) * (EE/4);
        for (int k = j; k < n1; k += 384) p1[k] = z4;
    }
    if (j < 256)
        out[BB*TT*EE + ((j < EE) ? b0 : b1)*EE + (j & 127)] = s_h[j];
}

// ---------------------------------------------------------------------------
extern "C" void kernel_launch(void* const* d_in, const int* in_sizes, int n_in,
                              void* d_out, int out_size){
    const int*   item_ids = (const int*)  d_in[0];
    const int*   bsz      = (const int*)  d_in[1];
    const int*   lengths  = (const int*)  d_in[2];
    const float* emb      = (const float*)d_in[3];
    const float* W_ih     = (const float*)d_in[4];
    const float* W_hh     = (const float*)d_in[5];
    const float* b_ih     = (const float*)d_in[6];
    const float* b_hh     = (const float*)d_in[7];
    const float* h0       = (const float*)d_in[8];
    float* out = (float*)d_out;

    const int smem_bytes = (2*TT*G3 + 2*EE + 2*G3) * 4;   // 157696
    cudaFuncSetAttribute(k_xgscan, cudaFuncAttributeMaxDynamicSharedMemorySize,
                         smem_bytes);

    k_gather<<<1600, 128>>>(item_ids, bsz, lengths, emb);
    k_xgscan<<<BB/2, 384, smem_bytes>>>(W_ih, W_hh, b_ih, b_hh, h0,
                                        lengths, out);
}

// round 12
// speedup vs baseline: 1.7211x; 1.7211x over previous
#include <cuda_runtime.h>

#define BB 256
#define TT 50
#define MM 20
#define EE 128
#define G3 384
#define NS 40            // single-row CTAs (longest rows)
#define GRID 148         // NS + (256-NS)/2

typedef unsigned long long u64;

// scratch (no cudaMalloc allowed)
__device__ __align__(16) float g_ub[BB*TT*EE];   // basket means (B,T,E)

__device__ __forceinline__ void fma2(u64 &acc, u64 a, u64 b){
    asm("fma.rn.f32x2 %0, %1, %2, %0;" : "+l"(acc) : "l"(a), "l"(b));
}
__device__ __forceinline__ u64 add2(u64 a, u64 b){
    u64 r; asm("add.rn.f32x2 %0, %1, %2;" : "=l"(r) : "l"(a), "l"(b));
    return r;
}
__device__ __forceinline__ float hsum2(u64 v){
    float lo, hi;
    asm("mov.b64 {%0,%1}, %2;" : "=f"(lo), "=f"(hi) : "l"(v));
    return lo + hi;
}
__device__ __forceinline__ float sigf(float x){
    return __fdividef(1.f, 1.f + __expf(-x));
}
__device__ __forceinline__ float tanhfast(float x){
    return __fdividef(2.f, 1.f + __expf(-2.f*x)) - 1.f;
}
__device__ __forceinline__ int zero_dep(float x){
    int r;
    asm("{\n\t.reg .b32 t;\n\tmov.b32 t, %1;\n\tand.b32 %0, t, 0;\n\t}"
        : "=r"(r) : "f"(x));
    return r;
}

// dot of this thread's W row with a 128-float vector in SMEM (broadcast LDS)
__device__ __forceinline__ float dot_s(const u64* __restrict__ w,
                                       const float* __restrict__ src){
    u64 ca = 0ull, cb = 0ull;
    const ulonglong2* hp = (const ulonglong2*)src;
    #pragma unroll
    for (int k = 0; k < 32; ++k){
        ulonglong2 v = hp[k];
        fma2(ca, w[2*k  ], v.x);
        fma2(cb, w[2*k+1], v.y);
    }
    return hsum2(add2(ca, cb));
}

// ---------------------------------------------------------------------------
// K1: gather (measured ~5us, unchanged)
// ---------------------------------------------------------------------------
#define RED20(FLD) \
    ((((v[0].FLD+v[1].FLD)+(v[2].FLD+v[3].FLD))+((v[4].FLD+v[5].FLD)+(v[6].FLD+v[7].FLD))) \
    +(((v[8].FLD+v[9].FLD)+(v[10].FLD+v[11].FLD))+((v[12].FLD+v[13].FLD)+(v[14].FLD+v[15].FLD))) \
    +((v[16].FLD+v[17].FLD)+(v[18].FLD+v[19].FLD)))

__global__ void __launch_bounds__(128,2) k_gather(const int* __restrict__ ids,
                                                  const int* __restrict__ bsz,
                                                  const int* __restrict__ lens,
                                                  const float* __restrict__ emb){
    const int p    = blockIdx.x * 4 + (threadIdx.x >> 5);   // 0..6399
    const int lane = threadIdx.x & 31;
    const float4* e4 = (const float4*)emb;

    const int r0 = p, r1 = 12799 - p;
    const int b0g = r0 / TT, t0g = r0 - b0g*TT;
    const int b1g = r1 / TT, t1g = r1 - b1g*TT;
    const bool act0 = t0g < __ldg(lens + b0g);
    const bool act1 = t1g < __ldg(lens + b1g);

    float4 v[20], u[20];
    if (act0){
        const int4* ip = (const int4*)(ids + r0*MM);
        const int4 i0=__ldg(ip), i1=__ldg(ip+1), i2=__ldg(ip+2),
                   i3=__ldg(ip+3), i4=__ldg(ip+4);
        v[0]=__ldg(e4+i0.x*32+lane);  v[1]=__ldg(e4+i0.y*32+lane);
        v[2]=__ldg(e4+i0.z*32+lane);  v[3]=__ldg(e4+i0.w*32+lane);
        v[4]=__ldg(e4+i1.x*32+lane);  v[5]=__ldg(e4+i1.y*32+lane);
        v[6]=__ldg(e4+i1.z*32+lane);  v[7]=__ldg(e4+i1.w*32+lane);
        v[8]=__ldg(e4+i2.x*32+lane);  v[9]=__ldg(e4+i2.y*32+lane);
        v[10]=__ldg(e4+i2.z*32+lane); v[11]=__ldg(e4+i2.w*32+lane);
        v[12]=__ldg(e4+i3.x*32+lane); v[13]=__ldg(e4+i3.y*32+lane);
        v[14]=__ldg(e4+i3.z*32+lane); v[15]=__ldg(e4+i3.w*32+lane);
        v[16]=__ldg(e4+i4.x*32+lane); v[17]=__ldg(e4+i4.y*32+lane);
        v[18]=__ldg(e4+i4.z*32+lane); v[19]=__ldg(e4+i4.w*32+lane);
    }
    if (act1){
        const int4* ip = (const int4*)(ids + r1*MM);
        const int4 i0=__ldg(ip), i1=__ldg(ip+1), i2=__ldg(ip+2),
                   i3=__ldg(ip+3), i4=__ldg(ip+4);
        u[0]=__ldg(e4+i0.x*32+lane);  u[1]=__ldg(e4+i0.y*32+lane);
        u[2]=__ldg(e4+i0.z*32+lane);  u[3]=__ldg(e4+i0.w*32+lane);
        u[4]=__ldg(e4+i1.x*32+lane);  u[5]=__ldg(e4+i1.y*32+lane);
        u[6]=__ldg(e4+i1.z*32+lane);  u[7]=__ldg(e4+i1.w*32+lane);
        u[8]=__ldg(e4+i2.x*32+lane);  u[9]=__ldg(e4+i2.y*32+lane);
        u[10]=__ldg(e4+i2.z*32+lane); u[11]=__ldg(e4+i2.w*32+lane);
        u[12]=__ldg(e4+i3.x*32+lane); u[13]=__ldg(e4+i3.y*32+lane);
        u[14]=__ldg(e4+i3.z*32+lane); u[15]=__ldg(e4+i3.w*32+lane);
        u[16]=__ldg(e4+i4.x*32+lane); u[17]=__ldg(e4+i4.y*32+lane);
        u[18]=__ldg(e4+i4.z*32+lane); u[19]=__ldg(e4+i4.w*32+lane);
    }
    if (act0){
        const float inv = 1.0f / (float)__ldg(bsz + r0);
        float4 a;
        a.x = RED20(x)*inv; a.y = RED20(y)*inv; a.z = RED20(z)*inv; a.w = RED20(w)*inv;
        ((float4*)g_ub)[r0*32 + lane] = a;
    }
    if (act1){
        #pragma unroll
        for (int k = 0; k < 20; ++k) v[k] = u[k];
        const float inv = 1.0f / (float)__ldg(bsz + r1);
        float4 a;
        a.x = RED20(x)*inv; a.y = RED20(y)*inv; a.z = RED20(z)*inv; a.w = RED20(w)*inv;
        ((float4*)g_ub)[r1*32 + lane] = a;
    }
}

// ---------------------------------------------------------------------------
// K2: fused xg + scan. Singles+pairs scheduling:
//   bid <  NS : single row  b0 = bid              (len1 = 0)
//   bid >= NS : pair  b0 = bid, b1 = 255+NS-bid   (rows NS..147 / 148..255)
// Phase B: flat job list (len0+len1 rows), quad-buffered smem staging,
//          2 dots per barrier.
// Phase C: champion step code — dual conditional dots, srz via smem,
//          j>=256 gates (own xn/hn in regs), 2 barriers/step.
// SMEM: xg 2*50*384 + ub 4*128 + h 2*128 + srz 512 = 39680 fl = 158720 B
// ---------------------------------------------------------------------------
__global__ void __launch_bounds__(384,1) k_xgscan(
    const float* __restrict__ W_ih,
    const float* __restrict__ W_hh,
    const float* __restrict__ b_ih,
    const float* __restrict__ b_hh,
    const float* __restrict__ h0,
    const int*   __restrict__ lens,
    float*       __restrict__ out)
{
    extern __shared__ float smem[];
    float* s_xg  = smem;                   // [2][TT][G3]
    float* s_ub  = s_xg + 2*TT*G3;         // [4][EE] quad buffer
    float* s_h   = s_ub + 4*EE;            // [2][EE]
    float* s_srz = s_h + 2*EE;             // [512]

    const int j   = threadIdx.x;
    const int bid = blockIdx.x;
    const bool dual = (bid >= NS);
    const int b0 = bid;
    const int b1 = dual ? (255 + NS - bid) : bid;
    const int len0 = __ldg(lens + b0);
    const int len1 = dual ? __ldg(lens + b1) : 0;
    const int total = len0 + len1;

    u64 w[64];

    // ---------------- Phase B: xg -> SMEM, flat job list ----------------
    {
        const u64* wr = (const u64*)(W_ih + j*EE);
        #pragma unroll
        for (int k = 0; k < 64; ++k) w[k] = __ldg(wr + k);
    }
    const float bi = __ldg(b_ih + j);
    const int lane = j & 31, lw = j >> 5;

    if (lw < 2 && lw < total){                   // preload jobs 0,1
        const int rsel = (lw >= len0);
        const int t    = lw - (rsel ? len0 : 0);
        const int bb   = rsel ? b1 : b0;
        ((float4*)(s_ub + (lw & 3)*EE))[lane] =
            ((const float4*)(g_ub + (bb*TT + t)*EE))[lane];
    }
    __syncthreads();

    for (int i = 0; i < total; i += 2){
        float4 pf; bool hav = false;
        if (lw < 2){
            const int ii = i + 2 + lw;
            if (ii < total){
                const int rsel = (ii >= len0);
                const int t    = ii - (rsel ? len0 : 0);
                const int bb   = rsel ? b1 : b0;
                pf = ((const float4*)(g_ub + (bb*TT + t)*EE))[lane];
                hav = true;
            }
        }
        {
            const int rsel = (i >= len0);
            const int t    = i - (rsel ? len0 : 0);
            s_xg[(rsel*TT + t)*G3 + j] = dot_s(w, s_ub + (i & 3)*EE) + bi;
        }
        if (i + 1 < total){
            const int rsel = (i + 1 >= len0);
            const int t    = (i + 1) - (rsel ? len0 : 0);
            s_xg[(rsel*TT + t)*G3 + j] = dot_s(w, s_ub + ((i + 1) & 3)*EE) + bi;
        }
        if (hav)
            ((float4*)(s_ub + ((i + 2 + lw) & 3)*EE))[lane] = pf;
        __syncthreads();
    }

    // ---------------- Phase C: scan (champion step code) ----------------
    const int dep = zero_dep(s_xg[j]);           // keep W_hh load after phase B
    {
        const u64* wr = (const u64*)(W_hh + (j + dep)*EE);
        #pragma unroll
        for (int k = 0; k < 64; ++k) w[k] = __ldg(wr + k);
    }
    const float bh = __ldg(b_hh + j);

    if (j < EE){
        s_h[j]      = __ldg(h0 + b0*EE + j);
        s_h[EE + j] = dual ? __ldg(h0 + b1*EE + j) : 0.f;
    }
    __syncthreads();

    for (int t = 0; t < len0; ++t){
        const bool a1 = (t < len1);
        const float xg0 = s_xg[t*G3 + j];
        const float hg0 = dot_s(w, s_h) + bh;
        float xg1 = 0.f, hg1 = 0.f;
        if (a1){ xg1 = s_xg[(TT + t)*G3 + j]; hg1 = dot_s(w, s_h + EE) + bh; }

        if (j < 256){
            s_srz[j]       = hg0 + xg0;
            s_srz[256 + j] = hg1 + xg1;
        }
        __syncthreads();

        if (j >= 256){
            const int e = j - 256;
            {   // row 0 gates (always active: t < len0)
                const float r  = sigf(s_srz[e]);
                const float z  = sigf(s_srz[e + 128]);
                const float n  = tanhfast(xg0 + r * hg0);    // xn + r*hn
                const float hv = (1.f - z)*n + z * s_h[e];
                s_h[e] = hv;
                out[(b0*TT + t)*EE + e] = hv;
            }
            if (a1){
                const float r  = sigf(s_srz[256 + e]);
                const float z  = sigf(s_srz[384 + e]);
                const float n  = tanhfast(xg1 + r * hg1);
                const float hv = (1.f - z)*n + z * s_h[EE + e];
                s_h[EE + e] = hv;
                out[(b1*TT + t)*EE + e] = hv;
            }
        }
        __syncthreads();
    }

    // ---------------- epilogue: masked tail zeros + h_u ----------------
    {
        const float4 z4 = make_float4(0.f, 0.f, 0.f, 0.f);
        float4* p0 = (float4*)(out + (b0*TT + len0)*EE);
        const int n0 = (TT - len0) * (EE/4);
        for (int k = j; k < n0; k += 384) p0[k] = z4;
        if (dual){
            float4* p1 = (float4*)(out + (b1*TT + len1)*EE);
            const int n1 = (TT - len1) * (EE/4);
            for (int k = j; k < n1; k += 384) p1[k] = z4;
        }
    }
    if (j < EE)
        out[BB*TT*EE + b0*EE + j] = s_h[j];
    else if (dual && j < 256)
        out[BB*TT*EE + b1*EE + (j - EE)] = s_h[j];
}

// ---------------------------------------------------------------------------
extern "C" void kernel_launch(void* const* d_in, const int* in_sizes, int n_in,
                              void* d_out, int out_size){
    const int*   item_ids = (const int*)  d_in[0];
    const int*   bsz      = (const int*)  d_in[1];
    const int*   lengths  = (const int*)  d_in[2];
    const float* emb      = (const float*)d_in[3];
    const float* W_ih     = (const float*)d_in[4];
    const float* W_hh     = (const float*)d_in[5];
    const float* b_ih     = (const float*)d_in[6];
    const float* b_hh     = (const float*)d_in[7];
    const float* h0       = (const float*)d_in[8];
    float* out = (float*)d_out;

    const int smem_bytes = (2*TT*G3 + 4*EE + 2*EE + 512) * 4;   // 158720
    cudaFuncSetAttribute(k_xgscan, cudaFuncAttributeMaxDynamicSharedMemorySize,
                         smem_bytes);

    k_gather<<<1600, 128>>>(item_ids, bsz, lengths, emb);
    k_xgscan<<<GRID, 384, smem_bytes>>>(W_ih, W_hh, b_ih, b_hh, h0,
                                        lengths, out);
}